// round 4
// baseline (speedup 1.0000x reference)
#include <cuda_runtime.h>
#include <math.h>
#include <stdint.h>

// ---------------- problem constants ----------------
#define B_    32
#define S_    4096
#define HID_  5120
#define H_    16
#define DN_   128
#define DR_   64
#define DV_   128
#define QL_   1536
#define KL_   512
#define DK_   576
#define QKV_N (QL_ + KL_ + DR_)   // 2112
#define QB_N  (H_ * (DN_ + DR_))  // 3072
#define SCALE_ 0.07216878364870323f

#define SPLITS 16
#define CHUNK  (S_ / SPLITS)  // 256
#define TILE   32
#define NT     (CHUNK / TILE) // 8
#define KROW   580

// ---------------- f32x2 packed helpers ----------------
__device__ __forceinline__ unsigned long long ffma2(unsigned long long a,
                                                    unsigned long long b,
                                                    unsigned long long c) {
    unsigned long long d;
    asm("fma.rn.f32x2 %0, %1, %2, %3;" : "=l"(d) : "l"(a), "l"(b), "l"(c));
    return d;
}
__device__ __forceinline__ unsigned long long mul2(unsigned long long a,
                                                   unsigned long long b) {
    unsigned long long d;
    asm("mul.rn.f32x2 %0, %1, %2;" : "=l"(d) : "l"(a), "l"(b));
    return d;
}
__device__ __forceinline__ float sum2(unsigned long long a) {
    return __uint_as_float((unsigned)(a & 0xffffffffull)) +
           __uint_as_float((unsigned)(a >> 32));
}
__device__ __forceinline__ void unpack2(unsigned long long a, float& lo, float& hi) {
    lo = __uint_as_float((unsigned)(a & 0xffffffffull));
    hi = __uint_as_float((unsigned)(a >> 32));
}

// ---------------- cp.async / named-barrier helpers ----------------
__device__ __forceinline__ void cpa16(uint32_t dst, const void* src) {
    asm volatile("cp.async.cg.shared.global [%0], [%1], 16;\n" :: "r"(dst), "l"(src));
}
__device__ __forceinline__ void cp_commit() {
    asm volatile("cp.async.commit_group;\n");
}
template<int N> __device__ __forceinline__ void cp_wait() {
    asm volatile("cp.async.wait_group %0;\n" :: "n"(N));
}
__device__ __forceinline__ void bar_sync(int id, int cnt) {
    asm volatile("bar.sync %0, %1;" :: "r"(id), "r"(cnt) : "memory");
}
__device__ __forceinline__ void bar_arrive(int id, int cnt) {
    asm volatile("bar.arrive %0, %1;" :: "r"(id), "r"(cnt) : "memory");
}

// ---------------- device scratch ----------------
__device__ float g_p1[16][B_][QKV_N];
__device__ float g_qkv[B_][QKV_N];
__device__ float g_qa_n[B_][QL_];
__device__ float g_latent_n[B_][KL_];
__device__ float g_kpe[B_][DR_];
__device__ float g_p2[8][B_][QB_N];
__device__ float g_q[B_][QB_N];
__device__ float g_qfinal[B_][H_][DK_];
__device__ float g_pm[B_][H_][SPLITS];
__device__ float g_pl[B_][H_][SPLITS];
__device__ float g_pctx[B_][SPLITS][H_][KL_];
__device__ float g_ctx[B_][H_][KL_];
__device__ float g_p4[4][B_][H_ * DV_];
__device__ float g_attn[B_][H_ * DV_];
__device__ float g_p3[8][B_][HID_];

// ---------------- skinny GEMM (f32x2, cp.async pipelined) ----------------
__global__ void __launch_bounds__(256) gemm32(
    const float* __restrict__ A, int lda, long sAh,
    const float* __restrict__ B, int ldb, long sBh,
    float* __restrict__ C, int ldc, long sCh, long cPart,
    int kchunk)
{
    __shared__ float As2[2][32 * 72];
    __shared__ float Bs[2][32 * 68];

    const int n0 = blockIdx.x * 64;
    const int k0 = blockIdx.y * kchunk;
    const int h  = blockIdx.z;
    A += (long)h * sAh;
    B += (long)h * sBh + n0;
    C += (long)h * sCh + (long)blockIdx.y * cPart + n0;

    const int t  = threadIdx.x;
    const int tn = t & 15;
    const int tm = t >> 4;
    const int arow = t >> 3, ac4 = (t & 7) * 4;
    const int br   = t >> 4, bc4 = (t & 15) * 4;

    const int iters = kchunk >> 5;

    unsigned long long c00 = 0, c01 = 0, c10 = 0, c11 = 0;

    // prologue: loads for iteration 0
    float4 a_cur = *(const float4*)&A[(long)arow * lda + k0 + ac4];
    cpa16((uint32_t)__cvta_generic_to_shared(&Bs[0][br * 68 + bc4]),
          &B[(long)(k0 + br) * ldb + bc4]);
    cpa16((uint32_t)__cvta_generic_to_shared(&Bs[0][(br + 16) * 68 + bc4]),
          &B[(long)(k0 + br + 16) * ldb + bc4]);
    cp_commit();

    for (int it = 0; it < iters; it++) {
        const int p = it & 1;
        float4 a_nxt = a_cur;
        if (it + 1 < iters) {
            const int k = k0 + (it + 1) * 32;
            a_nxt = *(const float4*)&A[(long)arow * lda + k + ac4];
            cpa16((uint32_t)__cvta_generic_to_shared(&Bs[p ^ 1][br * 68 + bc4]),
                  &B[(long)(k + br) * ldb + bc4]);
            cpa16((uint32_t)__cvta_generic_to_shared(&Bs[p ^ 1][(br + 16) * 68 + bc4]),
                  &B[(long)(k + br + 16) * ldb + bc4]);
            cp_commit();
        }
        float* ad = &As2[p][arow * 72 + ac4 * 2];
        *(float2*)(ad + 0) = make_float2(a_cur.x, a_cur.x);
        *(float2*)(ad + 2) = make_float2(a_cur.y, a_cur.y);
        *(float2*)(ad + 4) = make_float2(a_cur.z, a_cur.z);
        *(float2*)(ad + 6) = make_float2(a_cur.w, a_cur.w);
        if (it + 1 < iters) cp_wait<1>(); else cp_wait<0>();
        __syncthreads();
        #pragma unroll
        for (int kk = 0; kk < 32; kk++) {
            unsigned long long a0 = *(const unsigned long long*)&As2[p][(tm * 2)     * 72 + kk * 2];
            unsigned long long a1 = *(const unsigned long long*)&As2[p][(tm * 2 + 1) * 72 + kk * 2];
            ulonglong2 b2 = *(const ulonglong2*)&Bs[p][kk * 68 + tn * 4];
            c00 = ffma2(a0, b2.x, c00); c01 = ffma2(a0, b2.y, c01);
            c10 = ffma2(a1, b2.x, c10); c11 = ffma2(a1, b2.y, c11);
        }
        __syncthreads();
        a_cur = a_nxt;
    }
    float4 o0, o1;
    unpack2(c00, o0.x, o0.y); unpack2(c01, o0.z, o0.w);
    unpack2(c10, o1.x, o1.y); unpack2(c11, o1.z, o1.w);
    *(float4*)&C[(long)(tm * 2)     * ldc + tn * 4] = o0;
    *(float4*)&C[(long)(tm * 2 + 1) * ldc + tn * 4] = o1;
}

// ---------------- split-K reduce ----------------
__global__ void reduceK(const float* __restrict__ parts, float* __restrict__ out,
                        int n, int nparts, long stride)
{
    for (int i = blockIdx.x * blockDim.x + threadIdx.x; i < n; i += gridDim.x * blockDim.x) {
        float s = 0.f;
        for (int j = 0; j < nparts; j++) s += parts[(long)j * stride + i];
        out[i] = s;
    }
}

// ---------------- rmsnorms + rope(k_pe) ----------------
__global__ void prep_kernel(const int* __restrict__ positions,
                            const float* __restrict__ q_w,
                            const float* __restrict__ kv_w)
{
    const int b = blockIdx.x, t = threadIdx.x;
    const float* row = &g_qkv[b][0];
    __shared__ float red[256];

    float ss = 0.f;
    for (int i = t; i < QL_; i += 256) { float v = row[i]; ss += v * v; }
    red[t] = ss; __syncthreads();
    for (int o = 128; o > 0; o >>= 1) { if (t < o) red[t] += red[t + o]; __syncthreads(); }
    float r1 = rsqrtf(red[0] / (float)QL_ + 1e-6f);
    __syncthreads();
    for (int i = t; i < QL_; i += 256) g_qa_n[b][i] = row[i] * r1 * q_w[i];

    ss = 0.f;
    for (int i = t; i < KL_; i += 256) { float v = row[QL_ + i]; ss += v * v; }
    red[t] = ss; __syncthreads();
    for (int o = 128; o > 0; o >>= 1) { if (t < o) red[t] += red[t + o]; __syncthreads(); }
    float r2 = rsqrtf(red[0] / (float)KL_ + 1e-6f);
    __syncthreads();
    for (int i = t; i < KL_; i += 256) g_latent_n[b][i] = row[QL_ + i] * r2 * kv_w[i];

    if (t < 32) {
        float x1 = row[QL_ + KL_ + 2 * t];
        float x2 = row[QL_ + KL_ + 2 * t + 1];
        float inv = (float)exp(-(double)(2 * t) / 64.0 * 9.210340371976184);
        float fr = (float)positions[b] * inv;
        float c = cosf(fr), s = sinf(fr);
        g_kpe[b][2 * t]     = x1 * c - x2 * s;
        g_kpe[b][2 * t + 1] = x2 * c + x1 * s;
    }
}

// ---------------- rope on q_pe ----------------
__global__ void rope_q(const int* __restrict__ positions)
{
    const int b = blockIdx.x, t = threadIdx.x;
    const float pos = (float)positions[b];
    for (int idx = t; idx < H_ * 32; idx += 256) {
        int h = idx >> 5, i = idx & 31;
        float x1 = g_q[b][h * 192 + 128 + 2 * i];
        float x2 = g_q[b][h * 192 + 128 + 2 * i + 1];
        float inv = (float)exp(-(double)(2 * i) / 64.0 * 9.210340371976184);
        float fr = pos * inv;
        float c = cosf(fr), s = sinf(fr);
        g_qfinal[b][h][512 + 2 * i]     = x1 * c - x2 * s;
        g_qfinal[b][h][512 + 2 * i + 1] = x2 * c + x1 * s;
    }
}

// ---------------- flash-decode attention v4: warp-specialized ----------------
// grid (SPLITS, B), 512 threads. Warps 0-7: stage + scores + softmax (producer).
// Warps 8-15: ctx accumulate (consumer). Named barriers:
//   bar 1: P(i) ready   (producer arrives, consumer syncs)
//   bar 2: K buf free   (consumer arrives, producer syncs)
//   bar 3: producer-internal (256)
// smem (floats):
//   sQ    [0,9216)   sK0 [9216,27776)  sK1 [27776,46336)
//   sSp   [46336,51456)
//   sPd0  [51456,52608)  sPd1 [52608,53760)
//   sCd0  [53760,53792)  sCd1 [53792,53824)
//   sM    [53824,53840)  sL   [53840,53856)
#define ATTN_SMEM_FLOATS 53856

__global__ void __launch_bounds__(512, 1) attn_kernel(
    const float* __restrict__ cache_l,
    const float* __restrict__ cache_r)
{
    extern __shared__ float sm[];
    float* sQ   = sm;
    float* sK0  = sm + 9216;
    float* sK1  = sm + 27776;
    float* sSp  = sm + 46336;
    float* sPd0 = sm + 51456;
    float* sPd1 = sm + 52608;
    float* sCd0 = sm + 53760;
    float* sCd1 = sm + 53792;
    float* sM   = sm + 53824;
    float* sL   = sm + 53840;

    const int split = blockIdx.x, b = blockIdx.y;
    const int t = threadIdx.x;
    const long bs = (long)b * S_;
    const float4* cl4 = (const float4*)cache_l;
    const float4* cr4 = (const float4*)cache_r;
    const int s0 = split * CHUNK;

    // all threads: load Q, init M/L
    for (int i = t; i < 2304; i += 512)
        ((float4*)sQ)[i] = ((const float4*)&g_qfinal[b][0][0])[i];
    if (t < 16) { sM[t] = -3.0e38f; sL[t] = 0.f; }
    __syncthreads();

    if (t < 256) {
        // ================= PRODUCER =================
        const int sr = t >> 3, sc = t & 7;   // staging: 32 rows x 8 chunks
        // stage tile 0
        {
            long row = bs + s0 + sr;
            const float4* ls = cl4 + row * 128;
            const float4* rs = cr4 + row * 16;
            uint32_t d = (uint32_t)__cvta_generic_to_shared(sK0 + sr * KROW) + sc * 288;
            #pragma unroll
            for (int j = 0; j < 18; j++) {
                int idx = sc * 18 + j;
                const float4* src = (idx < 128) ? (ls + idx) : (rs + idx - 128);
                cpa16(d + j * 16, src);
            }
            cp_commit();
        }

        for (int i = 0; i < NT; i++) {
            float* kb = (i & 1) ? sK1 : sK0;
            if (i >= 1) bar_sync(2, 512);            // ctx(i-1) released buf(~i&1)
            if (i + 1 < NT) {
                float* kn = (i & 1) ? sK0 : sK1;
                long row = bs + s0 + (i + 1) * TILE + sr;
                const float4* ls = cl4 + row * 128;
                const float4* rs = cr4 + row * 16;
                uint32_t d = (uint32_t)__cvta_generic_to_shared(kn + sr * KROW) + sc * 288;
                #pragma unroll
                for (int j = 0; j < 18; j++) {
                    int idx = sc * 18 + j;
                    const float4* src = (idx < 128) ? (ls + idx) : (rs + idx - 128);
                    cpa16(d + j * 16, src);
                }
                cp_commit();
                cp_wait<1>();
            } else {
                cp_wait<0>();
            }
            // patch the freshly-computed last token (row 31 of last tile of split 15)
            if (s0 + (i + 1) * TILE == S_ && t < 144) {
                float4 v = (t < 128) ? ((const float4*)&g_latent_n[b][0])[t]
                                     : ((const float4*)&g_kpe[b][0])[t - 128];
                *(float4*)&kb[31 * KROW + t * 4] = v;
            }
            bar_sync(3, 256);    // tile-i data visible to all producer threads

            // ---- scores: ds = warp (8 d-chunks of 72), hg = head-half, sg = s ----
            {
                const int ds = t >> 5, hg = (t >> 4) & 1, sg = t & 15;
                const float* kp0 = kb + sg * KROW + ds * 72;
                const float* kp1 = kb + (sg + 16) * KROW + ds * 72;
                const float* qp  = sQ + hg * 8 * 576 + ds * 72;
                unsigned long long a0[8], a1[8];
                #pragma unroll
                for (int h = 0; h < 8; h++) { a0[h] = 0ull; a1[h] = 0ull; }
                #pragma unroll 6
                for (int c = 0; c < 18; c++) {
                    ulonglong2 k0v = *(const ulonglong2*)(kp0 + c * 4);
                    ulonglong2 k1v = *(const ulonglong2*)(kp1 + c * 4);
                    #pragma unroll
                    for (int h = 0; h < 8; h++) {
                        ulonglong2 q = *(const ulonglong2*)(qp + h * 576 + c * 4);
                        a0[h] = ffma2(q.x, k0v.x, a0[h]);
                        a0[h] = ffma2(q.y, k0v.y, a0[h]);
                        a1[h] = ffma2(q.x, k1v.x, a1[h]);
                        a1[h] = ffma2(q.y, k1v.y, a1[h]);
                    }
                }
                float* d0 = sSp + (ds * 32 + sg) * 20 + hg * 8;
                float* d1 = sSp + (ds * 32 + sg + 16) * 20 + hg * 8;
                #pragma unroll
                for (int h = 0; h < 4; h++) {
                    *(float2*)(d0 + 2 * h) = make_float2(sum2(a0[2 * h]), sum2(a0[2 * h + 1]));
                    *(float2*)(d1 + 2 * h) = make_float2(sum2(a1[2 * h]), sum2(a1[2 * h + 1]));
                }
            }
            bar_sync(3, 256);

            // ---- softmax: warp w handles heads 2w, 2w+1 over 32 lanes ----
            {
                float* sPd = (i & 1) ? sPd1 : sPd0;
                float* sCd = (i & 1) ? sCd1 : sCd0;
                const int lane = t & 31;
                #pragma unroll
                for (int hh = 0; hh < 2; hh++) {
                    const int h = ((t >> 5) << 1) + hh;
                    float sc_ = 0.f;
                    #pragma unroll
                    for (int d = 0; d < 8; d++) sc_ += sSp[(d * 32 + lane) * 20 + h];
                    sc_ *= SCALE_;
                    float m = sc_;
                    #pragma unroll
                    for (int o = 16; o; o >>= 1)
                        m = fmaxf(m, __shfl_xor_sync(0xffffffffu, m, o));
                    float mold = sM[h];
                    float mnew = fmaxf(mold, m);
                    float p = expf(sc_ - mnew);
                    float l = p;
                    #pragma unroll
                    for (int o = 16; o; o >>= 1)
                        l += __shfl_xor_sync(0xffffffffu, l, o);
                    *(float2*)&sPd[lane * 36 + 2 * h] = make_float2(p, p);
                    if (lane == 0) {
                        float corr = expf(mold - mnew);
                        *(float2*)&sCd[2 * h] = make_float2(corr, corr);
                        sM[h] = mnew;
                        sL[h] = sL[h] * corr + l;
                    }
                }
            }
            bar_arrive(1, 512);   // P(i) ready
        }
        if (t < 16) {
            g_pm[b][t][split] = sM[t];
            g_pl[b][t][split] = sL[t];
        }
    } else {
        // ================= CONSUMER (ctx) =================
        const int u = t - 256;
        const int hq = u >> 7, cq = u & 127;
        unsigned long long acc[8][2];
        #pragma unroll
        for (int h = 0; h < 8; h++) { acc[h][0] = 0ull; acc[h][1] = 0ull; }

        for (int i = 0; i < NT; i++) {
            float* kb  = (i & 1) ? sK1 : sK0;
            float* sPd = (i & 1) ? sPd1 : sPd0;
            float* sCd = (i & 1) ? sCd1 : sCd0;
            bar_sync(1, 512);     // wait P(i)

            ulonglong2 cc0 = *(const ulonglong2*)&sCd[hq * 16 + 0];
            ulonglong2 cc1 = *(const ulonglong2*)&sCd[hq * 16 + 4];
            ulonglong2 cc2 = *(const ulonglong2*)&sCd[hq * 16 + 8];
            ulonglong2 cc3 = *(const ulonglong2*)&sCd[hq * 16 + 12];
            unsigned long long cr[8] = {cc0.x, cc0.y, cc1.x, cc1.y,
                                        cc2.x, cc2.y, cc3.x, cc3.y};
            #pragma unroll
            for (int h = 0; h < 8; h++) {
                acc[h][0] = mul2(acc[h][0], cr[h]);
                acc[h][1] = mul2(acc[h][1], cr[h]);
            }
            const float* kv = kb + cq * 4;
            const float* pb = sPd + hq * 16;
            #pragma unroll 4
            for (int si = 0; si < TILE; si++) {
                ulonglong2 v  = *(const ulonglong2*)(kv + si * KROW);
                ulonglong2 p0 = *(const ulonglong2*)(pb + si * 36 + 0);
                ulonglong2 p1 = *(const ulonglong2*)(pb + si * 36 + 4);
                ulonglong2 p2 = *(const ulonglong2*)(pb + si * 36 + 8);
                ulonglong2 p3 = *(const ulonglong2*)(pb + si * 36 + 12);
                acc[0][0] = ffma2(p0.x, v.x, acc[0][0]); acc[0][1] = ffma2(p0.x, v.y, acc[0][1]);
                acc[1][0] = ffma2(p0.y, v.x, acc[1][0]); acc[1][1] = ffma2(p0.y, v.y, acc[1][1]);
                acc[2][0] = ffma2(p1.x, v.x, acc[2][0]); acc[2][1] = ffma2(p1.x, v.y, acc[2][1]);
                acc[3][0] = ffma2(p1.y, v.x, acc[3][0]); acc[3][1] = ffma2(p1.y, v.y, acc[3][1]);
                acc[4][0] = ffma2(p2.x, v.x, acc[4][0]); acc[4][1] = ffma2(p2.x, v.y, acc[4][1]);
                acc[5][0] = ffma2(p2.y, v.x, acc[5][0]); acc[5][1] = ffma2(p2.y, v.y, acc[5][1]);
                acc[6][0] = ffma2(p3.x, v.x, acc[6][0]); acc[6][1] = ffma2(p3.x, v.y, acc[6][1]);
                acc[7][0] = ffma2(p3.y, v.x, acc[7][0]); acc[7][1] = ffma2(p3.y, v.y, acc[7][1]);
            }
            bar_arrive(2, 512);   // K buf i free
        }
        #pragma unroll
        for (int h = 0; h < 8; h++) {
            float4 o;
            unpack2(acc[h][0], o.x, o.y);
            unpack2(acc[h][1], o.z, o.w);
            *(float4*)&g_pctx[b][split][hq * 8 + h][cq * 4] = o;
        }
    }
}

// ---------------- combine split partials ----------------
__global__ void attn_reduce()
{
    const int h = blockIdx.x, b = blockIdx.y;
    const int t = threadIdx.x;  // 128 threads, float4 over 512 cols
    __shared__ float se[SPLITS];
    __shared__ float s_inv;
    if (t == 0) {
        float M = -1e30f;
        for (int i = 0; i < SPLITS; i++) M = fmaxf(M, g_pm[b][h][i]);
        float L = 0.f;
        for (int i = 0; i < SPLITS; i++) {
            float e = expf(g_pm[b][h][i] - M);
            se[i] = e;
            L += g_pl[b][h][i] * e;
        }
        s_inv = 1.0f / L;
    }
    __syncthreads();
    float4 o = make_float4(0.f, 0.f, 0.f, 0.f);
    for (int i = 0; i < SPLITS; i++) {
        float e = se[i];
        float4 v = ((const float4*)&g_pctx[b][i][h][0])[t];
        o.x += e * v.x; o.y += e * v.y; o.z += e * v.z; o.w += e * v.w;
    }
    float inv = s_inv;
    o.x *= inv; o.y *= inv; o.z *= inv; o.w *= inv;
    ((float4*)&g_ctx[b][h][0])[t] = o;
}

// ---------------- host launcher ----------------
extern "C" void kernel_launch(void* const* d_in, const int* in_sizes, int n_in,
                              void* d_out, int out_size)
{
    (void)in_sizes; (void)n_in; (void)out_size;
    const float* hidden    = (const float*)d_in[0];
    const int*   positions = (const int*)  d_in[1];
    const float* cache_l   = (const float*)d_in[2];
    const float* cache_r   = (const float*)d_in[3];
    const float* w_qkv_a   = (const float*)d_in[4];
    const float* q_norm_w  = (const float*)d_in[5];
    const float* w_q_b     = (const float*)d_in[6];
    const float* kv_norm_w = (const float*)d_in[7];
    const float* w_kc      = (const float*)d_in[8];
    const float* w_vc      = (const float*)d_in[9];
    const float* w_o       = (const float*)d_in[10];
    float* out = (float*)d_out;

    float *p1, *qkv, *qa_n, *p2, *q, *qf, *ctx, *p4, *attnb, *p3;
    cudaGetSymbolAddress((void**)&p1,    g_p1);
    cudaGetSymbolAddress((void**)&qkv,   g_qkv);
    cudaGetSymbolAddress((void**)&qa_n,  g_qa_n);
    cudaGetSymbolAddress((void**)&p2,    g_p2);
    cudaGetSymbolAddress((void**)&q,     g_q);
    cudaGetSymbolAddress((void**)&qf,    g_qfinal);
    cudaGetSymbolAddress((void**)&ctx,   g_ctx);
    cudaGetSymbolAddress((void**)&p4,    g_p4);
    cudaGetSymbolAddress((void**)&attnb, g_attn);
    cudaGetSymbolAddress((void**)&p3,    g_p3);

    const int ATTN_SMEM = ATTN_SMEM_FLOATS * 4;  // 215424 B
    cudaFuncSetAttribute(attn_kernel, cudaFuncAttributeMaxDynamicSharedMemorySize, ATTN_SMEM);

    // 1) qkv = hidden @ w_qkv_a   (split-K x16)
    gemm32<<<dim3(QKV_N / 64, 16, 1), 256>>>(hidden, HID_, 0, w_qkv_a, QKV_N, 0,
                                             p1, QKV_N, 0, 32L * QKV_N, HID_ / 16);
    reduceK<<<264, 256>>>(p1, qkv, B_ * QKV_N, 16, 32L * QKV_N);

    // 2) rmsnorms + rope(k_pe)
    prep_kernel<<<B_, 256>>>(positions, q_norm_w, kv_norm_w);

    // 3) q = rmsnorm(q_a) @ w_q_b  (split-K x8)
    gemm32<<<dim3(QB_N / 64, 8, 1), 256>>>(qa_n, QL_, 0, w_q_b, QB_N, 0,
                                           p2, QB_N, 0, 32L * QB_N, QL_ / 8);
    reduceK<<<264, 256>>>(p2, q, B_ * QB_N, 8, 32L * QB_N);

    // 4) rope(q_pe) -> qfinal[...,512:576]
    rope_q<<<B_, 256>>>(positions);

    // 5) q_abs = q_nope @ w_kc[h] -> qfinal[...,0:512]
    gemm32<<<dim3(KL_ / 64, 1, H_), 256>>>(q, QB_N, 192, w_kc, KL_, (long)DN_ * KL_,
                                           qf, H_ * DK_, DK_, 0, DN_);

    // 6) flash-decode attention (warp-specialized)
    attn_kernel<<<dim3(SPLITS, B_), 512, ATTN_SMEM>>>(cache_l, cache_r);
    attn_reduce<<<dim3(H_, B_), 128>>>();

    // 7) per-head value projection (split-K x4): attn = ctx @ w_vc[h]
    gemm32<<<dim3(DV_ / 64, 4, H_), 256>>>(ctx, H_ * KL_, KL_, w_vc, DV_, (long)KL_ * DV_,
                                           p4, H_ * DV_, DV_, 32L * H_ * DV_, KL_ / 4);
    reduceK<<<264, 256>>>(p4, attnb, B_ * H_ * DV_, 4, 32L * H_ * DV_);

    // 8) out = attn @ w_o   (split-K x8)
    gemm32<<<dim3(HID_ / 64, 8, 1), 256>>>(attnb, H_ * DV_, 0, w_o, HID_, 0,
                                           p3, HID_, 0, 32L * HID_, (H_ * DV_) / 8);
    reduceK<<<264, 256>>>(p3, out, B_ * HID_, 8, 32L * HID_);
}

// round 5
// speedup vs baseline: 1.1628x; 1.1628x over previous
#include <cuda_runtime.h>
#include <math.h>
#include <stdint.h>

// ---------------- problem constants ----------------
#define B_    32
#define S_    4096
#define HID_  5120
#define H_    16
#define DN_   128
#define DR_   64
#define DV_   128
#define QL_   1536
#define KL_   512
#define DK_   576
#define QKV_N (QL_ + KL_ + DR_)   // 2112
#define QB_N  (H_ * (DN_ + DR_))  // 3072
#define SCALE_ 0.07216878364870323f

#define SPLITS 16
#define CHUNK  (S_ / SPLITS)  // 256
#define TILE   32
#define NT     (CHUNK / TILE) // 8
#define KROW   580

// ---------------- f32x2 packed helpers ----------------
__device__ __forceinline__ unsigned long long ffma2(unsigned long long a,
                                                    unsigned long long b,
                                                    unsigned long long c) {
    unsigned long long d;
    asm("fma.rn.f32x2 %0, %1, %2, %3;" : "=l"(d) : "l"(a), "l"(b), "l"(c));
    return d;
}
__device__ __forceinline__ unsigned long long mul2(unsigned long long a,
                                                   unsigned long long b) {
    unsigned long long d;
    asm("mul.rn.f32x2 %0, %1, %2;" : "=l"(d) : "l"(a), "l"(b));
    return d;
}
__device__ __forceinline__ float sum2(unsigned long long a) {
    return __uint_as_float((unsigned)(a & 0xffffffffull)) +
           __uint_as_float((unsigned)(a >> 32));
}
__device__ __forceinline__ void unpack2(unsigned long long a, float& lo, float& hi) {
    lo = __uint_as_float((unsigned)(a & 0xffffffffull));
    hi = __uint_as_float((unsigned)(a >> 32));
}

// ---------------- cp.async helpers ----------------
__device__ __forceinline__ void cpa16(uint32_t dst, const void* src) {
    asm volatile("cp.async.cg.shared.global [%0], [%1], 16;\n" :: "r"(dst), "l"(src));
}
__device__ __forceinline__ void cp_commit() {
    asm volatile("cp.async.commit_group;\n");
}
template<int N> __device__ __forceinline__ void cp_wait() {
    asm volatile("cp.async.wait_group %0;\n" :: "n"(N));
}

// ---------------- device scratch ----------------
__device__ float g_p1[16][B_][QKV_N];
__device__ float g_qkv[B_][QKV_N];
__device__ float g_qa_n[B_][QL_];
__device__ float g_latent_n[B_][KL_];
__device__ float g_kpe[B_][DR_];
__device__ float g_p2[8][B_][QB_N];
__device__ float g_q[B_][QB_N];
__device__ float g_qfinal[B_][H_][DK_];
__device__ float g_pm[B_][H_][SPLITS];
__device__ float g_pl[B_][H_][SPLITS];
__device__ float g_pctx[B_][SPLITS][2][H_][KL_];
__device__ float g_ctx[B_][H_][KL_];
__device__ float g_p4[4][B_][H_ * DV_];
__device__ float g_attn[B_][H_ * DV_];
__device__ float g_p3[8][B_][HID_];

// ---------------- skinny GEMM (f32x2, cp.async pipelined) ----------------
__global__ void __launch_bounds__(256) gemm32(
    const float* __restrict__ A, int lda, long sAh,
    const float* __restrict__ B, int ldb, long sBh,
    float* __restrict__ C, int ldc, long sCh, long cPart,
    int kchunk)
{
    __shared__ float As2[2][32 * 72];
    __shared__ float Bs[2][32 * 68];

    const int n0 = blockIdx.x * 64;
    const int k0 = blockIdx.y * kchunk;
    const int h  = blockIdx.z;
    A += (long)h * sAh;
    B += (long)h * sBh + n0;
    C += (long)h * sCh + (long)blockIdx.y * cPart + n0;

    const int t  = threadIdx.x;
    const int tn = t & 15;
    const int tm = t >> 4;
    const int arow = t >> 3, ac4 = (t & 7) * 4;
    const int br   = t >> 4, bc4 = (t & 15) * 4;

    const int iters = kchunk >> 5;

    unsigned long long c00 = 0, c01 = 0, c10 = 0, c11 = 0;

    float4 a_cur = *(const float4*)&A[(long)arow * lda + k0 + ac4];
    cpa16((uint32_t)__cvta_generic_to_shared(&Bs[0][br * 68 + bc4]),
          &B[(long)(k0 + br) * ldb + bc4]);
    cpa16((uint32_t)__cvta_generic_to_shared(&Bs[0][(br + 16) * 68 + bc4]),
          &B[(long)(k0 + br + 16) * ldb + bc4]);
    cp_commit();

    for (int it = 0; it < iters; it++) {
        const int p = it & 1;
        float4 a_nxt = a_cur;
        if (it + 1 < iters) {
            const int k = k0 + (it + 1) * 32;
            a_nxt = *(const float4*)&A[(long)arow * lda + k + ac4];
            cpa16((uint32_t)__cvta_generic_to_shared(&Bs[p ^ 1][br * 68 + bc4]),
                  &B[(long)(k + br) * ldb + bc4]);
            cpa16((uint32_t)__cvta_generic_to_shared(&Bs[p ^ 1][(br + 16) * 68 + bc4]),
                  &B[(long)(k + br + 16) * ldb + bc4]);
            cp_commit();
        }
        float* ad = &As2[p][arow * 72 + ac4 * 2];
        *(float2*)(ad + 0) = make_float2(a_cur.x, a_cur.x);
        *(float2*)(ad + 2) = make_float2(a_cur.y, a_cur.y);
        *(float2*)(ad + 4) = make_float2(a_cur.z, a_cur.z);
        *(float2*)(ad + 6) = make_float2(a_cur.w, a_cur.w);
        if (it + 1 < iters) cp_wait<1>(); else cp_wait<0>();
        __syncthreads();
        #pragma unroll
        for (int kk = 0; kk < 32; kk++) {
            unsigned long long a0 = *(const unsigned long long*)&As2[p][(tm * 2)     * 72 + kk * 2];
            unsigned long long a1 = *(const unsigned long long*)&As2[p][(tm * 2 + 1) * 72 + kk * 2];
            ulonglong2 b2 = *(const ulonglong2*)&Bs[p][kk * 68 + tn * 4];
            c00 = ffma2(a0, b2.x, c00); c01 = ffma2(a0, b2.y, c01);
            c10 = ffma2(a1, b2.x, c10); c11 = ffma2(a1, b2.y, c11);
        }
        __syncthreads();
        a_cur = a_nxt;
    }
    float4 o0, o1;
    unpack2(c00, o0.x, o0.y); unpack2(c01, o0.z, o0.w);
    unpack2(c10, o1.x, o1.y); unpack2(c11, o1.z, o1.w);
    *(float4*)&C[(long)(tm * 2)     * ldc + tn * 4] = o0;
    *(float4*)&C[(long)(tm * 2 + 1) * ldc + tn * 4] = o1;
}

// ---------------- split-K reduce ----------------
__global__ void reduceK(const float* __restrict__ parts, float* __restrict__ out,
                        int n, int nparts, long stride)
{
    for (int i = blockIdx.x * blockDim.x + threadIdx.x; i < n; i += gridDim.x * blockDim.x) {
        float s = 0.f;
        for (int j = 0; j < nparts; j++) s += parts[(long)j * stride + i];
        out[i] = s;
    }
}

// ---------------- rmsnorms + rope(k_pe) ----------------
__global__ void prep_kernel(const int* __restrict__ positions,
                            const float* __restrict__ q_w,
                            const float* __restrict__ kv_w)
{
    const int b = blockIdx.x, t = threadIdx.x;
    const float* row = &g_qkv[b][0];
    __shared__ float red[256];

    float ss = 0.f;
    for (int i = t; i < QL_; i += 256) { float v = row[i]; ss += v * v; }
    red[t] = ss; __syncthreads();
    for (int o = 128; o > 0; o >>= 1) { if (t < o) red[t] += red[t + o]; __syncthreads(); }
    float r1 = rsqrtf(red[0] / (float)QL_ + 1e-6f);
    __syncthreads();
    for (int i = t; i < QL_; i += 256) g_qa_n[b][i] = row[i] * r1 * q_w[i];

    ss = 0.f;
    for (int i = t; i < KL_; i += 256) { float v = row[QL_ + i]; ss += v * v; }
    red[t] = ss; __syncthreads();
    for (int o = 128; o > 0; o >>= 1) { if (t < o) red[t] += red[t + o]; __syncthreads(); }
    float r2 = rsqrtf(red[0] / (float)KL_ + 1e-6f);
    __syncthreads();
    for (int i = t; i < KL_; i += 256) g_latent_n[b][i] = row[QL_ + i] * r2 * kv_w[i];

    if (t < 32) {
        float x1 = row[QL_ + KL_ + 2 * t];
        float x2 = row[QL_ + KL_ + 2 * t + 1];
        float inv = (float)exp(-(double)(2 * t) / 64.0 * 9.210340371976184);
        float fr = (float)positions[b] * inv;
        float c = cosf(fr), s = sinf(fr);
        g_kpe[b][2 * t]     = x1 * c - x2 * s;
        g_kpe[b][2 * t + 1] = x2 * c + x1 * s;
    }
}

// ---------------- rope on q_pe ----------------
__global__ void rope_q(const int* __restrict__ positions)
{
    const int b = blockIdx.x, t = threadIdx.x;
    const float pos = (float)positions[b];
    for (int idx = t; idx < H_ * 32; idx += 256) {
        int h = idx >> 5, i = idx & 31;
        float x1 = g_q[b][h * 192 + 128 + 2 * i];
        float x2 = g_q[b][h * 192 + 128 + 2 * i + 1];
        float inv = (float)exp(-(double)(2 * i) / 64.0 * 9.210340371976184);
        float fr = pos * inv;
        float c = cosf(fr), s = sinf(fr);
        g_qfinal[b][h][512 + 2 * i]     = x1 * c - x2 * s;
        g_qfinal[b][h][512 + 2 * i + 1] = x2 * c + x1 * s;
    }
}

// ---------------- flash-decode attention v5 ----------------
// R3 structure (monolithic phases, cp.async double-buffer), but scores use
// ALL 512 threads: 16 d-splits x 36 floats (9 float4-chunks).
// smem (floats):
//   sQ   [0,9216)   sK0 [9216,27776)  sK1 [27776,46336)
//   sSp  [46336,55552)   16 ds x 32 s x 18 (h-padded)
//   sPd  [55552,56704)   32 s x 36 (dup P pairs)
//   sM   [56704,56720)  sL [56720,56736)  sCd [56736,56768)
#define ATTN_SMEM_FLOATS 56768

__global__ void __launch_bounds__(512, 1) attn_kernel(
    const float* __restrict__ cache_l,
    const float* __restrict__ cache_r)
{
    extern __shared__ float sm[];
    float* sQ  = sm;
    float* sK0 = sm + 9216;
    float* sK1 = sm + 27776;
    float* sSp = sm + 46336;
    float* sPd = sm + 55552;
    float* sM  = sm + 56704;
    float* sL  = sm + 56720;
    float* sCd = sm + 56736;

    const int split = blockIdx.x, b = blockIdx.y;
    const int t = threadIdx.x;
    const long bs = (long)b * S_;
    const float4* cl4 = (const float4*)cache_l;
    const float4* cr4 = (const float4*)cache_r;
    const int s0 = split * CHUNK;

    // staging coords (32 rows x 16 chunks)
    const int sr = t >> 4, scg = t & 15;

    // load Q (16x576 = 2304 float4)
    for (int i = t; i < 2304; i += 512)
        ((float4*)sQ)[i] = ((const float4*)&g_qfinal[b][0][0])[i];
    if (t < 16) { sM[t] = -3.0e38f; sL[t] = 0.f; }

    unsigned long long acc[8][2];
    #pragma unroll
    for (int h = 0; h < 8; h++) { acc[h][0] = 0ull; acc[h][1] = 0ull; }

    // prologue: prefetch tile 0 into sK0
    {
        long row = bs + s0 + sr;
        const float4* ls = cl4 + row * 128;
        const float4* rs = cr4 + row * 16;
        uint32_t d = (uint32_t)__cvta_generic_to_shared(sK0 + sr * KROW + scg * 4);
        #pragma unroll
        for (int j = 0; j < 8; j++) cpa16(d + j * 256, ls + scg + j * 16);
        cpa16(d + 8 * 256, rs + scg);
        cp_commit();
    }

    for (int tile = 0; tile < NT; tile++) {
        float* kb = (tile & 1) ? sK1 : sK0;
        if (tile + 1 < NT) {
            float* kn = (tile & 1) ? sK0 : sK1;
            long row = bs + s0 + (tile + 1) * TILE + sr;
            const float4* ls = cl4 + row * 128;
            const float4* rs = cr4 + row * 16;
            uint32_t d = (uint32_t)__cvta_generic_to_shared(kn + sr * KROW + scg * 4);
            #pragma unroll
            for (int j = 0; j < 8; j++) cpa16(d + j * 256, ls + scg + j * 16);
            cpa16(d + 8 * 256, rs + scg);
            cp_commit();
            cp_wait<1>();
        } else {
            cp_wait<0>();
        }
        __syncthreads();

        // patch the freshly-computed last token (row 31, last tile of split 15)
        if (s0 + tile * TILE + TILE == S_) {
            if (t < 144) {
                float4 v = (t < 128) ? ((const float4*)&g_latent_n[b][0])[t]
                                     : ((const float4*)&g_kpe[b][0])[t - 128];
                *(float4*)&kb[31 * KROW + t * 4] = v;
            }
            __syncthreads();
        }

        // ---- scores, ALL 512 threads: ds = t>>5 (16 x 36 floats), hg, sg ----
        {
            const int ds = t >> 5, hg = (t >> 4) & 1, sg = t & 15;
            const float* kp0 = kb + sg * KROW + ds * 36;
            const float* kp1 = kb + (sg + 16) * KROW + ds * 36;
            const float* qp  = sQ + hg * 8 * 576 + ds * 36;
            unsigned long long a0[8], a1[8];
            #pragma unroll
            for (int h = 0; h < 8; h++) { a0[h] = 0ull; a1[h] = 0ull; }
            #pragma unroll
            for (int c = 0; c < 9; c++) {
                ulonglong2 k0v = *(const ulonglong2*)(kp0 + c * 4);
                ulonglong2 k1v = *(const ulonglong2*)(kp1 + c * 4);
                #pragma unroll
                for (int h = 0; h < 8; h++) {
                    ulonglong2 q = *(const ulonglong2*)(qp + h * 576 + c * 4);
                    a0[h] = ffma2(q.x, k0v.x, a0[h]);
                    a0[h] = ffma2(q.y, k0v.y, a0[h]);
                    a1[h] = ffma2(q.x, k1v.x, a1[h]);
                    a1[h] = ffma2(q.y, k1v.y, a1[h]);
                }
            }
            float* d0 = sSp + (ds * 32 + sg) * 18 + hg * 8;
            float* d1 = sSp + (ds * 32 + sg + 16) * 18 + hg * 8;
            #pragma unroll
            for (int h = 0; h < 4; h++) {
                *(float2*)(d0 + 2 * h) = make_float2(sum2(a0[2 * h]), sum2(a0[2 * h + 1]));
                *(float2*)(d1 + 2 * h) = make_float2(sum2(a1[2 * h]), sum2(a1[2 * h + 1]));
            }
        }
        __syncthreads();

        // ---- softmax: h = t>>5 (16 heads), s = t&31 ----
        {
            const int h = t >> 5, s = t & 31;
            float sc = 0.f;
            #pragma unroll
            for (int d = 0; d < 16; d++) sc += sSp[(d * 32 + s) * 18 + h];
            sc *= SCALE_;
            float m = sc;
            #pragma unroll
            for (int o = 16; o; o >>= 1) m = fmaxf(m, __shfl_xor_sync(0xffffffffu, m, o));
            float mold = sM[h];
            float mnew = fmaxf(mold, m);
            float p = __expf(sc - mnew);
            float l = p;
            #pragma unroll
            for (int o = 16; o; o >>= 1) l += __shfl_xor_sync(0xffffffffu, l, o);
            *(float2*)&sPd[s * 36 + 2 * h] = make_float2(p, p);
            if (s == 0) {
                float corr = __expf(mold - mnew);
                *(float2*)&sCd[2 * h] = make_float2(corr, corr);
                sM[h] = mnew;
                sL[h] = sL[h] * corr + l;
            }
        }
        __syncthreads();

        // ---- ctx: hq = t>>8, sp = (t>>7)&1, cq = t&127 ----
        {
            const int hq = t >> 8, sp = (t >> 7) & 1, cq = t & 127;
            ulonglong2 cc0 = *(const ulonglong2*)&sCd[hq * 16 + 0];
            ulonglong2 cc1 = *(const ulonglong2*)&sCd[hq * 16 + 4];
            ulonglong2 cc2 = *(const ulonglong2*)&sCd[hq * 16 + 8];
            ulonglong2 cc3 = *(const ulonglong2*)&sCd[hq * 16 + 12];
            unsigned long long cr[8] = {cc0.x, cc0.y, cc1.x, cc1.y,
                                        cc2.x, cc2.y, cc3.x, cc3.y};
            #pragma unroll
            for (int h = 0; h < 8; h++) {
                acc[h][0] = mul2(acc[h][0], cr[h]);
                acc[h][1] = mul2(acc[h][1], cr[h]);
            }
            const float* kv = kb + sp * 16 * KROW + cq * 4;
            const float* pb = sPd + sp * 16 * 36 + hq * 16;
            #pragma unroll 4
            for (int si = 0; si < 16; si++) {
                ulonglong2 v  = *(const ulonglong2*)(kv + si * KROW);
                ulonglong2 p0 = *(const ulonglong2*)(pb + si * 36 + 0);
                ulonglong2 p1 = *(const ulonglong2*)(pb + si * 36 + 4);
                ulonglong2 p2 = *(const ulonglong2*)(pb + si * 36 + 8);
                ulonglong2 p3 = *(const ulonglong2*)(pb + si * 36 + 12);
                acc[0][0] = ffma2(p0.x, v.x, acc[0][0]); acc[0][1] = ffma2(p0.x, v.y, acc[0][1]);
                acc[1][0] = ffma2(p0.y, v.x, acc[1][0]); acc[1][1] = ffma2(p0.y, v.y, acc[1][1]);
                acc[2][0] = ffma2(p1.x, v.x, acc[2][0]); acc[2][1] = ffma2(p1.x, v.y, acc[2][1]);
                acc[3][0] = ffma2(p1.y, v.x, acc[3][0]); acc[3][1] = ffma2(p1.y, v.y, acc[3][1]);
                acc[4][0] = ffma2(p2.x, v.x, acc[4][0]); acc[4][1] = ffma2(p2.x, v.y, acc[4][1]);
                acc[5][0] = ffma2(p2.y, v.x, acc[5][0]); acc[5][1] = ffma2(p2.y, v.y, acc[5][1]);
                acc[6][0] = ffma2(p3.x, v.x, acc[6][0]); acc[6][1] = ffma2(p3.x, v.y, acc[6][1]);
                acc[7][0] = ffma2(p3.y, v.x, acc[7][0]); acc[7][1] = ffma2(p3.y, v.y, acc[7][1]);
            }
        }
        __syncthreads();
    }

    // ---- write partials ----
    {
        const int hq = t >> 8, sp = (t >> 7) & 1, cq = t & 127;
        #pragma unroll
        for (int h = 0; h < 8; h++) {
            float4 o;
            unpack2(acc[h][0], o.x, o.y);
            unpack2(acc[h][1], o.z, o.w);
            *(float4*)&g_pctx[b][split][sp][hq * 8 + h][cq * 4] = o;
        }
    }
    if (t < 16) {
        g_pm[b][t][split] = sM[t];
        g_pl[b][t][split] = sL[t];
    }
}

// ---------------- combine split partials ----------------
__global__ void attn_reduce()
{
    const int h = blockIdx.x, b = blockIdx.y;
    const int t = threadIdx.x;  // 128 threads, float4 over 512 cols
    __shared__ float se[SPLITS];
    __shared__ float s_inv;
    if (t == 0) {
        float M = -1e30f;
        for (int i = 0; i < SPLITS; i++) M = fmaxf(M, g_pm[b][h][i]);
        float L = 0.f;
        for (int i = 0; i < SPLITS; i++) {
            float e = __expf(g_pm[b][h][i] - M);
            se[i] = e;
            L += g_pl[b][h][i] * e;
        }
        s_inv = 1.0f / L;
    }
    __syncthreads();
    float4 o = make_float4(0.f, 0.f, 0.f, 0.f);
    for (int i = 0; i < SPLITS; i++) {
        float e = se[i];
        float4 v0 = ((const float4*)&g_pctx[b][i][0][h][0])[t];
        float4 v1 = ((const float4*)&g_pctx[b][i][1][h][0])[t];
        o.x += e * (v0.x + v1.x); o.y += e * (v0.y + v1.y);
        o.z += e * (v0.z + v1.z); o.w += e * (v0.w + v1.w);
    }
    float inv = s_inv;
    o.x *= inv; o.y *= inv; o.z *= inv; o.w *= inv;
    ((float4*)&g_ctx[b][h][0])[t] = o;
}

// ---------------- host launcher ----------------
extern "C" void kernel_launch(void* const* d_in, const int* in_sizes, int n_in,
                              void* d_out, int out_size)
{
    (void)in_sizes; (void)n_in; (void)out_size;
    const float* hidden    = (const float*)d_in[0];
    const int*   positions = (const int*)  d_in[1];
    const float* cache_l   = (const float*)d_in[2];
    const float* cache_r   = (const float*)d_in[3];
    const float* w_qkv_a   = (const float*)d_in[4];
    const float* q_norm_w  = (const float*)d_in[5];
    const float* w_q_b     = (const float*)d_in[6];
    const float* kv_norm_w = (const float*)d_in[7];
    const float* w_kc      = (const float*)d_in[8];
    const float* w_vc      = (const float*)d_in[9];
    const float* w_o       = (const float*)d_in[10];
    float* out = (float*)d_out;

    float *p1, *qkv, *qa_n, *p2, *q, *qf, *ctx, *p4, *attnb, *p3;
    cudaGetSymbolAddress((void**)&p1,    g_p1);
    cudaGetSymbolAddress((void**)&qkv,   g_qkv);
    cudaGetSymbolAddress((void**)&qa_n,  g_qa_n);
    cudaGetSymbolAddress((void**)&p2,    g_p2);
    cudaGetSymbolAddress((void**)&q,     g_q);
    cudaGetSymbolAddress((void**)&qf,    g_qfinal);
    cudaGetSymbolAddress((void**)&ctx,   g_ctx);
    cudaGetSymbolAddress((void**)&p4,    g_p4);
    cudaGetSymbolAddress((void**)&attnb, g_attn);
    cudaGetSymbolAddress((void**)&p3,    g_p3);

    const int ATTN_SMEM = ATTN_SMEM_FLOATS * 4;  // 227072 B
    cudaFuncSetAttribute(attn_kernel, cudaFuncAttributeMaxDynamicSharedMemorySize, ATTN_SMEM);

    // 1) qkv = hidden @ w_qkv_a   (split-K x16)
    gemm32<<<dim3(QKV_N / 64, 16, 1), 256>>>(hidden, HID_, 0, w_qkv_a, QKV_N, 0,
                                             p1, QKV_N, 0, 32L * QKV_N, HID_ / 16);
    reduceK<<<264, 256>>>(p1, qkv, B_ * QKV_N, 16, 32L * QKV_N);

    // 2) rmsnorms + rope(k_pe)
    prep_kernel<<<B_, 256>>>(positions, q_norm_w, kv_norm_w);

    // 3) q = rmsnorm(q_a) @ w_q_b  (split-K x8)
    gemm32<<<dim3(QB_N / 64, 8, 1), 256>>>(qa_n, QL_, 0, w_q_b, QB_N, 0,
                                           p2, QB_N, 0, 32L * QB_N, QL_ / 8);
    reduceK<<<264, 256>>>(p2, q, B_ * QB_N, 8, 32L * QB_N);

    // 4) rope(q_pe) -> qfinal[...,512:576]
    rope_q<<<B_, 256>>>(positions);

    // 5) q_abs = q_nope @ w_kc[h] -> qfinal[...,0:512]
    gemm32<<<dim3(KL_ / 64, 1, H_), 256>>>(q, QB_N, 192, w_kc, KL_, (long)DN_ * KL_,
                                           qf, H_ * DK_, DK_, 0, DN_);

    // 6) flash-decode attention
    attn_kernel<<<dim3(SPLITS, B_), 512, ATTN_SMEM>>>(cache_l, cache_r);
    attn_reduce<<<dim3(H_, B_), 128>>>();

    // 7) per-head value projection (split-K x4): attn = ctx @ w_vc[h]
    gemm32<<<dim3(DV_ / 64, 4, H_), 256>>>(ctx, H_ * KL_, KL_, w_vc, DV_, (long)KL_ * DV_,
                                           p4, H_ * DV_, DV_, 32L * H_ * DV_, KL_ / 4);
    reduceK<<<264, 256>>>(p4, attnb, B_ * H_ * DV_, 4, 32L * H_ * DV_);

    // 8) out = attn @ w_o   (split-K x8)
    gemm32<<<dim3(HID_ / 64, 8, 1), 256>>>(attnb, H_ * DV_, 0, w_o, HID_, 0,
                                           p3, HID_, 0, 32L * HID_, (H_ * DV_) / 8);
    reduceK<<<264, 256>>>(p3, out, B_ * HID_, 8, 32L * HID_);
}